// round 1
// baseline (speedup 1.0000x reference)
#include <cuda_runtime.h>
#include <cstdint>
#include <cstddef>

#define ATOMS   50000
#define EDGES   800000
#define NB      128     // n_atom_basis == n_filters
#define NG      64      // n_gauss
#define TS      4096    // filter table samples over [0, CUTOFF]
#define CUTOFFF 5.0f

// Scratch (no allocations allowed in kernel_launch)
__device__ float g_tab[(size_t)TS * NB];        // 2 MB   W(d) lookup table (bias folded in)
__device__ float g_rf [(size_t)ATOMS * NB];     // 25.6MB r @ W_af
__device__ float g_acc[(size_t)ATOMS * NB];     // 25.6MB segment-sum accumulator
__device__ float g_mid[(size_t)ATOMS * NB];     // 25.6MB ssp(acc@W_d1+b1)

// ---------------------------------------------------------------------------
__global__ void zero_acc_kernel() {
    size_t n4 = (size_t)ATOMS * NB / 4;
    float4 z = make_float4(0.f, 0.f, 0.f, 0.f);
    float4* p = reinterpret_cast<float4*>(g_acc);
    for (size_t i = blockIdx.x * (size_t)blockDim.x + threadIdx.x; i < n4;
         i += (size_t)gridDim.x * blockDim.x)
        p[i] = z;
}

// ---------------------------------------------------------------------------
// Build W(d) table: tab[s][:] = exp(coeff*(d_s - off)^2) @ W_df2 + b_df2
// One warp per sample row; each lane owns 4 columns.
__global__ void build_table_kernel(const float* __restrict__ Wdf2,
                                   const float* __restrict__ bdf2) {
    int row  = blockIdx.x * 4 + (threadIdx.x >> 5);
    int lane = threadIdx.x & 31;
    if (row >= TS) return;
    float d = (float)row * (CUTOFFF / (float)(TS - 1));
    const float width = 5.0f / 63.0f;
    const float coeff = -0.5f / (width * width);
    float4 acc = reinterpret_cast<const float4*>(bdf2)[lane];
    #pragma unroll 8
    for (int k = 0; k < NG; k++) {
        float off = (float)k * (5.0f / 63.0f);
        float dd  = d - off;
        float gk  = __expf(coeff * dd * dd);
        float4 w  = reinterpret_cast<const float4*>(Wdf2 + k * NB)[lane];
        acc.x += gk * w.x; acc.y += gk * w.y;
        acc.z += gk * w.z; acc.w += gk * w.w;
    }
    reinterpret_cast<float4*>(g_tab + (size_t)row * NB)[lane] = acc;
}

// ---------------------------------------------------------------------------
// Edge kernel: warp per edge. Lerp filter row from table, gather rf[src],
// modulate, vector-atomic into acc[dst].
__global__ void edge_kernel(const float* __restrict__ dist,
                            const int*   __restrict__ idx,
                            int E) {
    int lane   = threadIdx.x & 31;
    int warp   = (blockIdx.x * blockDim.x + threadIdx.x) >> 5;
    int nwarps = (gridDim.x * blockDim.x) >> 5;
    const float scale = (float)(TS - 1) / CUTOFFF;   // 819.0f
    for (int e = warp; e < E; e += nwarps) {
        float d = __ldg(&dist[e]);
        int2 de = *reinterpret_cast<const int2*>(idx + 2 * (size_t)e);
        int dst = de.x, src = de.y;
        float pos = d * scale;
        int i = (int)pos;
        if (i > TS - 2) i = TS - 2;
        if (i < 0) i = 0;
        float f = pos - (float)i;
        float4 w0 = reinterpret_cast<const float4*>(g_tab + (size_t)i * NB)[lane];
        float4 w1 = reinterpret_cast<const float4*>(g_tab + (size_t)(i + 1) * NB)[lane];
        float4 rv = reinterpret_cast<const float4*>(g_rf + (size_t)src * NB)[lane];
        float4 v;
        v.x = fmaf(f, w1.x - w0.x, w0.x) * rv.x;
        v.y = fmaf(f, w1.y - w0.y, w0.y) * rv.y;
        v.z = fmaf(f, w1.z - w0.z, w0.z) * rv.z;
        v.w = fmaf(f, w1.w - w0.w, w0.w) * rv.w;
        float* dp = g_acc + (size_t)dst * NB + lane * 4;
        asm volatile("red.global.add.v4.f32 [%0], {%1,%2,%3,%4};"
                     :: "l"(dp), "f"(v.x), "f"(v.y), "f"(v.z), "f"(v.w)
                     : "memory");
    }
}

// ---------------------------------------------------------------------------
__device__ __forceinline__ float sspf(float x) {
    // shifted softplus: log1p(exp(x)) - ln2, numerically stable
    float ax = fabsf(x);
    return fmaxf(x, 0.0f) + log1pf(__expf(-ax)) - 0.69314718f;
}

// C[M,128] = act(A[M,128] @ B[128,128] + bias)
// Block 256 threads, 64-row tiles, grid-stride over tiles. B cached in smem.
template <bool SSP, bool BIAS>
__global__ void gemm128_kernel(const float* __restrict__ A,
                               const float* __restrict__ B,
                               const float* __restrict__ bias,
                               float* __restrict__ C, int M) {
    extern __shared__ float sm[];
    float* Bs = sm;                  // [128][128]
    float* As = sm + 128 * 128;      // [64][132] padded
    const int ASTR = 132;

    for (int idx = threadIdx.x; idx < 128 * 32; idx += blockDim.x)
        reinterpret_cast<float4*>(Bs)[idx] = reinterpret_cast<const float4*>(B)[idx];

    int colg = threadIdx.x & 15;     // 8 output cols
    int rowg = threadIdx.x >> 4;     // 4 output rows
    float bb[8];
    #pragma unroll
    for (int j = 0; j < 8; j++) bb[j] = 0.f;
    if (BIAS) {
        float4 b0 = reinterpret_cast<const float4*>(bias)[colg * 2];
        float4 b1 = reinterpret_cast<const float4*>(bias)[colg * 2 + 1];
        bb[0] = b0.x; bb[1] = b0.y; bb[2] = b0.z; bb[3] = b0.w;
        bb[4] = b1.x; bb[5] = b1.y; bb[6] = b1.z; bb[7] = b1.w;
    }
    __syncthreads();

    int tiles = (M + 63) >> 6;
    for (int t = blockIdx.x; t < tiles; t += gridDim.x) {
        int row0 = t << 6;
        for (int idx = threadIdx.x; idx < 64 * 32; idx += blockDim.x) {
            int rr = idx >> 5, kk = idx & 31;
            float4 v = make_float4(0.f, 0.f, 0.f, 0.f);
            if (row0 + rr < M)
                v = reinterpret_cast<const float4*>(A + (size_t)(row0 + rr) * NB)[kk];
            reinterpret_cast<float4*>(&As[rr * ASTR])[kk] = v;
        }
        __syncthreads();

        float acc[4][8];
        #pragma unroll
        for (int r = 0; r < 4; r++)
            #pragma unroll
            for (int j = 0; j < 8; j++) acc[r][j] = 0.f;

        #pragma unroll 2
        for (int k = 0; k < 128; k += 4) {
            float4 a4[4];
            #pragma unroll
            for (int r = 0; r < 4; r++)
                a4[r] = *reinterpret_cast<float4*>(&As[(rowg * 4 + r) * ASTR + k]);
            #pragma unroll
            for (int kk = 0; kk < 4; kk++) {
                float4 b0 = *reinterpret_cast<float4*>(&Bs[(k + kk) * 128 + colg * 8]);
                float4 b1 = *reinterpret_cast<float4*>(&Bs[(k + kk) * 128 + colg * 8 + 4]);
                #pragma unroll
                for (int r = 0; r < 4; r++) {
                    float av = (kk == 0) ? a4[r].x : (kk == 1) ? a4[r].y
                             : (kk == 2) ? a4[r].z : a4[r].w;
                    acc[r][0] = fmaf(av, b0.x, acc[r][0]);
                    acc[r][1] = fmaf(av, b0.y, acc[r][1]);
                    acc[r][2] = fmaf(av, b0.z, acc[r][2]);
                    acc[r][3] = fmaf(av, b0.w, acc[r][3]);
                    acc[r][4] = fmaf(av, b1.x, acc[r][4]);
                    acc[r][5] = fmaf(av, b1.y, acc[r][5]);
                    acc[r][6] = fmaf(av, b1.z, acc[r][6]);
                    acc[r][7] = fmaf(av, b1.w, acc[r][7]);
                }
            }
        }

        #pragma unroll
        for (int r = 0; r < 4; r++) {
            int row = row0 + rowg * 4 + r;
            if (row < M) {
                float o[8];
                #pragma unroll
                for (int j = 0; j < 8; j++) {
                    float x = acc[r][j] + bb[j];
                    o[j] = SSP ? sspf(x) : x;
                }
                float4* cp = reinterpret_cast<float4*>(C + (size_t)row * NB + colg * 8);
                cp[0] = make_float4(o[0], o[1], o[2], o[3]);
                cp[1] = make_float4(o[4], o[5], o[6], o[7]);
            }
        }
        __syncthreads();
    }
}

// ---------------------------------------------------------------------------
extern "C" void kernel_launch(void* const* d_in, const int* in_sizes, int n_in,
                              void* d_out, int out_size) {
    const float* r     = (const float*)d_in[0];
    const float* e     = (const float*)d_in[1];
    const int*   a     = (const int*)  d_in[2];
    // d_in[3], d_in[4] = W_df1, b_df1: dead in the reference (overwritten)
    const float* W_df2 = (const float*)d_in[5];
    const float* b_df2 = (const float*)d_in[6];
    const float* W_af  = (const float*)d_in[7];
    const float* W_d1  = (const float*)d_in[8];
    const float* b_d1  = (const float*)d_in[9];
    const float* W_d2  = (const float*)d_in[10];
    const float* b_d2  = (const float*)d_in[11];
    float* out = (float*)d_out;

    float *rf, *acc, *mid;
    cudaGetSymbolAddress((void**)&rf,  g_rf);
    cudaGetSymbolAddress((void**)&acc, g_acc);
    cudaGetSymbolAddress((void**)&mid, g_mid);

    const int smem = (128 * 128 + 64 * 132) * 4;  // 99328 B
    cudaFuncSetAttribute(gemm128_kernel<false, false>,
                         cudaFuncAttributeMaxDynamicSharedMemorySize, smem);
    cudaFuncSetAttribute(gemm128_kernel<true, true>,
                         cudaFuncAttributeMaxDynamicSharedMemorySize, smem);
    cudaFuncSetAttribute(gemm128_kernel<false, true>,
                         cudaFuncAttributeMaxDynamicSharedMemorySize, smem);

    int E = in_sizes[1];          // 800000
    int M = in_sizes[0] / NB;     // 50000

    zero_acc_kernel<<<512, 256>>>();
    build_table_kernel<<<TS / 4, 128>>>(W_df2, b_df2);
    gemm128_kernel<false, false><<<296, 256, smem>>>(r, W_af, nullptr, rf, M);
    edge_kernel<<<2048, 256>>>(e, a, E);
    gemm128_kernel<true, true><<<296, 256, smem>>>(acc, W_d1, b_d1, mid, M);
    gemm128_kernel<false, true><<<296, 256, smem>>>(mid, W_d2, b_d2, out, M);
}

// round 2
// speedup vs baseline: 1.2544x; 1.2544x over previous
#include <cuda_runtime.h>
#include <cstdint>
#include <cstddef>

#define ATOMS   50000
#define EDGES   800000
#define NB      128     // n_atom_basis == n_filters
#define NG      64      // n_gauss
#define TS      4096    // filter table samples over [0, CUTOFF]
#define CUTOFFF 5.0f

// Scratch (no allocations allowed in kernel_launch)
__device__ float g_tab[(size_t)TS * NB];        // 2 MB   W(d) lookup table (bias folded in)
__device__ float g_rf [(size_t)ATOMS * NB];     // 25.6MB r @ W_af
__device__ float g_acc[(size_t)ATOMS * NB];     // 25.6MB segment-sum accumulator
__device__ float g_mid[(size_t)ATOMS * NB];     // 25.6MB ssp(acc@W_d1+b1)

// ---------------------------------------------------------------------------
__global__ void zero_acc_kernel() {
    size_t n4 = (size_t)ATOMS * NB / 4;
    float4 z = make_float4(0.f, 0.f, 0.f, 0.f);
    float4* p = reinterpret_cast<float4*>(g_acc);
    for (size_t i = blockIdx.x * (size_t)blockDim.x + threadIdx.x; i < n4;
         i += (size_t)gridDim.x * blockDim.x)
        p[i] = z;
}

// ---------------------------------------------------------------------------
// Build W(d) table: tab[s][:] = exp(coeff*(d_s - off)^2) @ W_df2 + b_df2
__global__ void build_table_kernel(const float* __restrict__ Wdf2,
                                   const float* __restrict__ bdf2) {
    int row  = blockIdx.x * 4 + (threadIdx.x >> 5);
    int lane = threadIdx.x & 31;
    if (row >= TS) return;
    float d = (float)row * (CUTOFFF / (float)(TS - 1));
    const float width = 5.0f / 63.0f;
    const float coeff = -0.5f / (width * width);
    float4 acc = reinterpret_cast<const float4*>(bdf2)[lane];
    #pragma unroll 8
    for (int k = 0; k < NG; k++) {
        float off = (float)k * (5.0f / 63.0f);
        float dd  = d - off;
        float gk  = __expf(coeff * dd * dd);
        float4 w  = reinterpret_cast<const float4*>(Wdf2 + k * NB)[lane];
        acc.x += gk * w.x; acc.y += gk * w.y;
        acc.z += gk * w.z; acc.w += gk * w.w;
    }
    reinterpret_cast<float4*>(g_tab + (size_t)row * NB)[lane] = acc;
}

// ---------------------------------------------------------------------------
// Edge kernel (unchanged from R1): warp per edge; lerp filter row, gather
// rf[src], modulate, vector-atomic into acc[dst].
__global__ void edge_kernel(const float* __restrict__ dist,
                            const int*   __restrict__ idx,
                            int E) {
    int lane   = threadIdx.x & 31;
    int warp   = (blockIdx.x * blockDim.x + threadIdx.x) >> 5;
    int nwarps = (gridDim.x * blockDim.x) >> 5;
    const float scale = (float)(TS - 1) / CUTOFFF;
    for (int e = warp; e < E; e += nwarps) {
        float d = __ldg(&dist[e]);
        int2 de = *reinterpret_cast<const int2*>(idx + 2 * (size_t)e);
        int dst = de.x, src = de.y;
        float pos = d * scale;
        int i = (int)pos;
        if (i > TS - 2) i = TS - 2;
        if (i < 0) i = 0;
        float f = pos - (float)i;
        float4 w0 = reinterpret_cast<const float4*>(g_tab + (size_t)i * NB)[lane];
        float4 w1 = reinterpret_cast<const float4*>(g_tab + (size_t)(i + 1) * NB)[lane];
        float4 rv = reinterpret_cast<const float4*>(g_rf + (size_t)src * NB)[lane];
        float4 v;
        v.x = fmaf(f, w1.x - w0.x, w0.x) * rv.x;
        v.y = fmaf(f, w1.y - w0.y, w0.y) * rv.y;
        v.z = fmaf(f, w1.z - w0.z, w0.z) * rv.z;
        v.w = fmaf(f, w1.w - w0.w, w0.w) * rv.w;
        float* dp = g_acc + (size_t)dst * NB + lane * 4;
        asm volatile("red.global.add.v4.f32 [%0], {%1,%2,%3,%4};"
                     :: "l"(dp), "f"(v.x), "f"(v.y), "f"(v.z), "f"(v.w)
                     : "memory");
    }
}

// ---------------------------------------------------------------------------
__device__ __forceinline__ float sspf(float x) {
    float ax = fabsf(x);
    return fmaxf(x, 0.0f) + log1pf(__expf(-ax)) - 0.69314718f;
}

__device__ __forceinline__ uint32_t f2tf32(float x) {
    uint32_t r;
    asm("cvt.rna.tf32.f32 %0, %1;" : "=r"(r) : "f"(x));
    return r;
}

__device__ __forceinline__ void mma_tf32(float* c, const uint32_t* a,
                                         uint32_t b0, uint32_t b1) {
    asm volatile(
        "mma.sync.aligned.m16n8k8.row.col.f32.tf32.tf32.f32 "
        "{%0,%1,%2,%3}, {%4,%5,%6,%7}, {%8,%9}, {%0,%1,%2,%3};"
        : "+f"(c[0]), "+f"(c[1]), "+f"(c[2]), "+f"(c[3])
        : "r"(a[0]), "r"(a[1]), "r"(a[2]), "r"(a[3]), "r"(b0), "r"(b1));
}

// C[M,128] = act(A[M,128] @ B[128,128] + bias), tf32 tensor-core GEMM.
// Block = 256 threads (8 warps), block tile 128x128, warp tile 32x64.
// A,B staged in smem as tf32 with padded strides (132 / 136 words) for
// conflict-free fragment loads.
#define ASTRIDE 132
#define BSTRIDE 136
template <bool SSP, bool BIAS>
__global__ __launch_bounds__(256, 1)
void gemm_tf32_kernel(const float* __restrict__ A,
                      const float* __restrict__ B,
                      const float* __restrict__ bias,
                      float* __restrict__ C, int M) {
    extern __shared__ uint32_t smu[];
    uint32_t* As = smu;                   // [128][ASTRIDE]
    uint32_t* Bs = smu + 128 * ASTRIDE;   // [128][BSTRIDE]

    int tid  = threadIdx.x;
    int row0 = blockIdx.x * 128;

    // Stage B (tf32-converted)
    for (int i = tid; i < 128 * 32; i += 256) {
        int r = i >> 5, c = i & 31;
        float4 v = reinterpret_cast<const float4*>(B + r * NB)[c];
        uint4 t = make_uint4(f2tf32(v.x), f2tf32(v.y), f2tf32(v.z), f2tf32(v.w));
        *reinterpret_cast<uint4*>(&Bs[r * BSTRIDE + c * 4]) = t;
    }
    // Stage A (tf32-converted, zero-padded past M)
    for (int i = tid; i < 128 * 32; i += 256) {
        int r = i >> 5, c = i & 31;
        float4 v = make_float4(0.f, 0.f, 0.f, 0.f);
        if (row0 + r < M)
            v = reinterpret_cast<const float4*>(A + (size_t)(row0 + r) * NB)[c];
        uint4 t = make_uint4(f2tf32(v.x), f2tf32(v.y), f2tf32(v.z), f2tf32(v.w));
        *reinterpret_cast<uint4*>(&As[r * ASTRIDE + c * 4]) = t;
    }
    __syncthreads();

    int warp = tid >> 5, lane = tid & 31;
    int wm = warp & 3;          // 0..3 : M position (32 rows each)
    int wn = warp >> 2;         // 0..1 : N position (64 cols each)
    int g = lane >> 2, tig = lane & 3;

    float acc[2][8][4];
    #pragma unroll
    for (int mt = 0; mt < 2; mt++)
        #pragma unroll
        for (int nt = 0; nt < 8; nt++)
            #pragma unroll
            for (int j = 0; j < 4; j++) acc[mt][nt][j] = 0.f;

    #pragma unroll
    for (int k0 = 0; k0 < 128; k0 += 8) {
        uint32_t af[2][4];
        #pragma unroll
        for (int mt = 0; mt < 2; mt++) {
            int r = wm * 32 + mt * 16;
            af[mt][0] = As[(r + g)     * ASTRIDE + k0 + tig];
            af[mt][1] = As[(r + g + 8) * ASTRIDE + k0 + tig];
            af[mt][2] = As[(r + g)     * ASTRIDE + k0 + tig + 4];
            af[mt][3] = As[(r + g + 8) * ASTRIDE + k0 + tig + 4];
        }
        #pragma unroll
        for (int nt = 0; nt < 8; nt++) {
            int n = wn * 64 + nt * 8;
            uint32_t b0 = Bs[(k0 + tig)     * BSTRIDE + n + g];
            uint32_t b1 = Bs[(k0 + tig + 4) * BSTRIDE + n + g];
            mma_tf32(acc[0][nt], af[0], b0, b1);
            mma_tf32(acc[1][nt], af[1], b0, b1);
        }
    }

    // Epilogue: bias + optional shifted-softplus, write float2 per frag row
    #pragma unroll
    for (int mt = 0; mt < 2; mt++) {
        #pragma unroll
        for (int nt = 0; nt < 8; nt++) {
            int col = wn * 64 + nt * 8 + 2 * tig;
            float2 bv = make_float2(0.f, 0.f);
            if (BIAS) bv = *reinterpret_cast<const float2*>(bias + col);
            int r1 = row0 + wm * 32 + mt * 16 + g;
            int r2 = r1 + 8;
            if (r1 < M) {
                float x0 = acc[mt][nt][0] + bv.x;
                float x1 = acc[mt][nt][1] + bv.y;
                float2 o = make_float2(SSP ? sspf(x0) : x0, SSP ? sspf(x1) : x1);
                *reinterpret_cast<float2*>(C + (size_t)r1 * NB + col) = o;
            }
            if (r2 < M) {
                float x0 = acc[mt][nt][2] + bv.x;
                float x1 = acc[mt][nt][3] + bv.y;
                float2 o = make_float2(SSP ? sspf(x0) : x0, SSP ? sspf(x1) : x1);
                *reinterpret_cast<float2*>(C + (size_t)r2 * NB + col) = o;
            }
        }
    }
}

// ---------------------------------------------------------------------------
extern "C" void kernel_launch(void* const* d_in, const int* in_sizes, int n_in,
                              void* d_out, int out_size) {
    const float* r     = (const float*)d_in[0];
    const float* e     = (const float*)d_in[1];
    const int*   a     = (const int*)  d_in[2];
    // d_in[3], d_in[4] = W_df1, b_df1: dead in the reference (overwritten)
    const float* W_df2 = (const float*)d_in[5];
    const float* b_df2 = (const float*)d_in[6];
    const float* W_af  = (const float*)d_in[7];
    const float* W_d1  = (const float*)d_in[8];
    const float* b_d1  = (const float*)d_in[9];
    const float* W_d2  = (const float*)d_in[10];
    const float* b_d2  = (const float*)d_in[11];
    float* out = (float*)d_out;

    float *rf, *acc, *mid;
    cudaGetSymbolAddress((void**)&rf,  g_rf);
    cudaGetSymbolAddress((void**)&acc, g_acc);
    cudaGetSymbolAddress((void**)&mid, g_mid);

    const int smem = (128 * ASTRIDE + 128 * BSTRIDE) * 4;  // 137216 B
    cudaFuncSetAttribute(gemm_tf32_kernel<false, false>,
                         cudaFuncAttributeMaxDynamicSharedMemorySize, smem);
    cudaFuncSetAttribute(gemm_tf32_kernel<true, true>,
                         cudaFuncAttributeMaxDynamicSharedMemorySize, smem);
    cudaFuncSetAttribute(gemm_tf32_kernel<false, true>,
                         cudaFuncAttributeMaxDynamicSharedMemorySize, smem);

    int E = in_sizes[1];          // 800000
    int M = in_sizes[0] / NB;     // 50000
    int nblk = (M + 127) / 128;   // 391

    zero_acc_kernel<<<512, 256>>>();
    build_table_kernel<<<TS / 4, 128>>>(W_df2, b_df2);
    gemm_tf32_kernel<false, false><<<nblk, 256, smem>>>(r, W_af, nullptr, rf, M);
    edge_kernel<<<2048, 256>>>(e, a, E);
    gemm_tf32_kernel<true, true><<<nblk, 256, smem>>>(acc, W_d1, b_d1, mid, M);
    gemm_tf32_kernel<false, true><<<nblk, 256, smem>>>(mid, W_d2, b_d2, out, M);
}